// round 15
// baseline (speedup 1.0000x reference)
#include <cuda_runtime.h>
#include <cuda_bf16.h>
#include <cstdint>

#define FMAX 20908

// Repacked per-face record: 4 x float4 = 64B, 128B-aligned so each record
// lies in one 128B line.
// chunk0=(t00,t01,t02,t10) chunk1=(t11,t12,t20,t21) chunk2=(t22,n0,n1,n2) chunk3=pad
__device__ __align__(128) float4 g_face_pack[FMAX * 4];

__global__ __launch_bounds__(256) void repack_kernel(
    const float* __restrict__ triangles,    // [F,3,3]
    const float* __restrict__ face_normals, // [F,3]
    int F)
{
    int i = blockIdx.x * blockDim.x + threadIdx.x;
    if (i >= F * 3) return;
    int f = i / 3;
    int c = i - 3 * f;
    const float* t = triangles + (size_t)f * 9;
    float4 v;
    if (c == 0)      v = make_float4(t[0], t[1], t[2], t[3]);
    else if (c == 1) v = make_float4(t[4], t[5], t[6], t[7]);
    else {
        const float* n = face_normals + (size_t)f * 3;
        v = make_float4(t[8], n[0], n[1], n[2]);
    }
    g_face_pack[4*f + c] = v;
}

__device__ __forceinline__ void cp_async16(uint32_t smem_addr, const void* gptr) {
    asm volatile("cp.async.ca.shared.global [%0], [%1], 16;"
                 :: "r"(smem_addr), "l"(gptr) : "memory");
}
__device__ __forceinline__ void bulk_store(void* gptr, uint32_t smem_addr, uint32_t bytes) {
    asm volatile("cp.async.bulk.global.shared::cta.bulk_group [%0], [%1], %2;"
                 :: "l"(gptr), "r"(smem_addr), "r"(bytes) : "memory");
}

// R11 structure (1 point/thread, 256 threads = 8 warps, cp.async gather) with
// the store path moved off l1tex: outputs staged in smem (conflict-free STS),
// then 5 per-warp TMA bulk stores (dense, contiguous per section).
__global__ __launch_bounds__(256) void sd_tma_kernel(
    const float* __restrict__ points,        // [Q,3]
    const int*   __restrict__ closest_faces, // [Q]
    const float* __restrict__ closest_bcs,   // [Q,3]
    float* __restrict__ out,
    int Q)
{
    // 8 warps x 32 records x 48B (stride 48B -> conflict-free LDS.128)
    __shared__ float4 s_face[8 * 96];        // 12 KB
    // per-warp output staging: [0,32) sd | [32,128) rn | [128,224) cp |
    // [224,256) cf | [256,352) bc   (352 floats = 1408B, all 16B-aligned)
    __shared__ float s_out[8][352];          // 11 KB

    int tid  = threadIdx.x;
    int lane = tid & 31;
    int wrp  = tid >> 5;
    int q    = blockIdx.x * blockDim.x + tid;
    int wb   = q - lane;
    if (wb >= Q) return;
    bool full = (wb + 32 <= Q);

    float* rn_out = out + (size_t)Q;
    float* cp_out = out + (size_t)4 * Q;
    float* cf_out = out + (size_t)7 * Q;
    float* bc_out = out + (size_t)8 * Q;

    if (full) {
        // ---- fire-and-forget cooperative gather via cp.async ----
        uint32_t sw_base = (uint32_t)__cvta_generic_to_shared(s_face + wrp * 96);
        int c    = lane & 3;
        int pgrp = lane >> 2;
        #pragma unroll
        for (int r = 0; r < 4; r++) {
            int p_local = 8*r + pgrp;
            int fp = closest_faces[wb + p_local];   // L1-hot broadcast line
            if (c < 3) {
                cp_async16(sw_base + (uint32_t)(p_local * 48 + c * 16),
                           &g_face_pack[4*(size_t)fp + c]);
            }
        }
        asm volatile("cp.async.commit_group;" ::: "memory");

        // ---- streaming loads overlap the async copies ----
        int f = closest_faces[q];
        float c0 = closest_bcs[3*q + 0];
        float c1 = closest_bcs[3*q + 1];
        float c2 = closest_bcs[3*q + 2];
        float p0 = points[3*q + 0];
        float p1 = points[3*q + 1];
        float p2 = points[3*q + 2];

        asm volatile("cp.async.wait_group 0;" ::: "memory");
        __syncwarp();

        const float4* sw = s_face + wrp * 96;
        float4 v0 = sw[lane*3 + 0];
        float4 v1 = sw[lane*3 + 1];
        float4 v2 = sw[lane*3 + 2];

        float b0 = fminf(fmaxf(c0, 0.0f), 1.0f);
        float b1 = fminf(fmaxf(c1, 0.0f), 1.0f);
        float b2 = fminf(fmaxf(c2, 0.0f), 1.0f);

        // v0=(t00,t01,t02,t10) v1=(t11,t12,t20,t21) v2=(t22,n0,n1,n2)
        float cpx = fmaf(v0.x, b0, fmaf(v0.w, b1, v1.z * b2));
        float cpy = fmaf(v0.y, b0, fmaf(v1.x, b1, v1.w * b2));
        float cpz = fmaf(v0.z, b0, fmaf(v1.y, b1, v2.x * b2));

        float r0 = cpx - p0;
        float r1 = cpy - p1;
        float r2 = cpz - p2;

        float sq   = fmaf(r0, r0, fmaf(r1, r1, r2 * r2));
        float dist = sqrtf(sq);
        float inv  = (dist == 0.0f) ? 1.0f : (1.0f / dist);

        float rn0 = r0 * inv, rn1 = r1 * inv, rn2 = r2 * inv;

        float dot  = fmaf(r0, v2.y, fmaf(r1, v2.z, r2 * v2.w));
        float sign = (dot > 0.0f) ? -1.0f : 1.0f;

        // ---- stage outputs in smem (all conflict-free patterns) ----
        float* so = s_out[wrp];
        so[lane]            = sign * dist;
        so[32 + 3*lane + 0] = rn0;
        so[32 + 3*lane + 1] = rn1;
        so[32 + 3*lane + 2] = rn2;
        so[128 + 3*lane + 0] = cpx;
        so[128 + 3*lane + 1] = cpy;
        so[128 + 3*lane + 2] = cpz;
        so[224 + lane]      = (float)f;
        so[256 + 3*lane + 0] = b0;
        so[256 + 3*lane + 1] = b1;
        so[256 + 3*lane + 2] = b2;
        __syncwarp();

        // ---- per-warp TMA bulk stores (dense contiguous sections) ----
        if (lane == 0) {
            asm volatile("fence.proxy.async.shared::cta;" ::: "memory");
            uint32_t so_base = (uint32_t)__cvta_generic_to_shared(so);
            size_t wb3 = (size_t)3 * wb;
            bulk_store(out + wb,       so_base,            128);
            bulk_store(rn_out + wb3,   so_base + 32*4,     384);
            bulk_store(cp_out + wb3,   so_base + 128*4,    384);
            bulk_store(cf_out + wb,    so_base + 224*4,    128);
            bulk_store(bc_out + wb3,   so_base + 256*4,    384);
            asm volatile("cp.async.bulk.commit_group;" ::: "memory");
            // hold until TMA has read the smem staging (CTA must not exit first)
            asm volatile("cp.async.bulk.wait_group.read 0;" ::: "memory");
        }
    } else if (q < Q) {
        // scalar fallback (partial warp; unused when Q % 32 == 0)
        int f = closest_faces[q];
        float b0 = fminf(fmaxf(closest_bcs[3*q+0], 0.0f), 1.0f);
        float b1 = fminf(fmaxf(closest_bcs[3*q+1], 0.0f), 1.0f);
        float b2 = fminf(fmaxf(closest_bcs[3*q+2], 0.0f), 1.0f);
        float p0 = points[3*q+0], p1 = points[3*q+1], p2 = points[3*q+2];
        float4 v0 = __ldg(&g_face_pack[4*(size_t)f + 0]);
        float4 v1 = __ldg(&g_face_pack[4*(size_t)f + 1]);
        float4 v2 = __ldg(&g_face_pack[4*(size_t)f + 2]);
        float cpx = fmaf(v0.x, b0, fmaf(v0.w, b1, v1.z * b2));
        float cpy = fmaf(v0.y, b0, fmaf(v1.x, b1, v1.w * b2));
        float cpz = fmaf(v0.z, b0, fmaf(v1.y, b1, v2.x * b2));
        float r0 = cpx - p0, r1 = cpy - p1, r2 = cpz - p2;
        float sq = fmaf(r0, r0, fmaf(r1, r1, r2 * r2));
        float dist = sqrtf(sq);
        float inv = (dist == 0.0f) ? 1.0f : (1.0f / dist);
        float dot = fmaf(r0, v2.y, fmaf(r1, v2.z, r2 * v2.w));
        float sign = (dot > 0.0f) ? -1.0f : 1.0f;
        out[q] = sign * dist;
        cf_out[q] = (float)f;
        rn_out[3*q+0] = r0*inv; rn_out[3*q+1] = r1*inv; rn_out[3*q+2] = r2*inv;
        cp_out[3*q+0] = cpx; cp_out[3*q+1] = cpy; cp_out[3*q+2] = cpz;
        bc_out[3*q+0] = b0;  bc_out[3*q+1] = b1;  bc_out[3*q+2] = b2;
    }
}

extern "C" void kernel_launch(void* const* d_in, const int* in_sizes, int n_in,
                              void* d_out, int out_size) {
    const float* triangles     = (const float*)d_in[0];
    const float* face_normals  = (const float*)d_in[1];
    const float* points        = (const float*)d_in[2];
    const int*   closest_faces = (const int*)d_in[3];
    const float* closest_bcs   = (const float*)d_in[4];
    float* out = (float*)d_out;

    int F = in_sizes[0] / 9;
    int Q = in_sizes[3];

    int Fc = F > FMAX ? FMAX : F;
    repack_kernel<<<(Fc * 3 + 255) / 256, 256>>>(triangles, face_normals, Fc);

    int blocks = (Q + 255) / 256;
    sd_tma_kernel<<<blocks, 256>>>(points, closest_faces, closest_bcs, out, Q);
}

// round 16
// speedup vs baseline: 1.0290x; 1.0290x over previous
#include <cuda_runtime.h>
#include <cuda_bf16.h>
#include <cstdint>

#define FMAX 20908

// Repacked per-face record: 4 x float4 = 64B, 128B-aligned so each record
// lies in one 128B line.
// chunk0=(t00,t01,t02,t10) chunk1=(t11,t12,t20,t21) chunk2=(t22,n0,n1,n2) chunk3=pad
__device__ __align__(128) float4 g_face_pack[FMAX * 4];

__global__ __launch_bounds__(256) void repack_kernel(
    const float* __restrict__ triangles,    // [F,3,3]
    const float* __restrict__ face_normals, // [F,3]
    int F)
{
    int i = blockIdx.x * blockDim.x + threadIdx.x;
    if (i >= F * 3) return;
    int f = i / 3;
    int c = i - 3 * f;
    const float* t = triangles + (size_t)f * 9;
    float4 v;
    if (c == 0)      v = make_float4(t[0], t[1], t[2], t[3]);
    else if (c == 1) v = make_float4(t[4], t[5], t[6], t[7]);
    else {
        const float* n = face_normals + (size_t)f * 3;
        v = make_float4(t[8], n[0], n[1], n[2]);
    }
    g_face_pack[4*f + c] = v;
}

__device__ __forceinline__ void cp_async16(uint32_t smem_addr, const void* gptr) {
    asm volatile("cp.async.ca.shared.global [%0], [%1], 16;"
                 :: "r"(smem_addr), "l"(gptr) : "memory");
}

// R11 structure (1 point/thread, 256 threads = 8 warps, cp.async gather), with
// the per-thread stream LDGs (points/bcs) replaced by two per-CTA TMA bulk
// loads into smem + conflict-free LDS.
__global__ __launch_bounds__(256) void sd_tmald_kernel(
    const float* __restrict__ points,        // [Q,3]
    const int*   __restrict__ closest_faces, // [Q]
    const float* __restrict__ closest_bcs,   // [Q,3]
    float* __restrict__ out,
    int Q)
{
    __shared__ float4 s_face[8 * 96];                 // 12 KB gather staging
    __shared__ float4 s_pts4[192];                    // 3 KB  points (256 pts)
    __shared__ float4 s_bcs4[192];                    // 3 KB  bcs
    __shared__ __align__(8) unsigned long long s_mbar;

    int tid  = threadIdx.x;
    int lane = tid & 31;
    int wrp  = tid >> 5;
    int cb   = blockIdx.x << 8;                       // CTA base point
    int q    = cb + tid;
    int wb   = q - lane;
    if (wb >= Q) return;                              // empty warps exit
    bool cta_full = (cb + 256 <= Q);
    bool full     = (wb + 32 <= Q);

    uint32_t mb = (uint32_t)__cvta_generic_to_shared(&s_mbar);

    if (cta_full) {
        if (tid == 0) {
            asm volatile("mbarrier.init.shared.b64 [%0], 1;" :: "r"(mb) : "memory");
        }
        __syncthreads();
        if (tid == 0) {
            asm volatile("mbarrier.arrive.expect_tx.shared.b64 _, [%0], 6144;"
                         :: "r"(mb) : "memory");
            uint32_t dp = (uint32_t)__cvta_generic_to_shared(s_pts4);
            uint32_t db = (uint32_t)__cvta_generic_to_shared(s_bcs4);
            const float* gp = points + (size_t)3 * cb;
            const float* gb = closest_bcs + (size_t)3 * cb;
            asm volatile(
                "cp.async.bulk.shared::cta.global.mbarrier::complete_tx::bytes [%0], [%1], 3072, [%2];"
                :: "r"(dp), "l"(gp), "r"(mb) : "memory");
            asm volatile(
                "cp.async.bulk.shared::cta.global.mbarrier::complete_tx::bytes [%0], [%1], 3072, [%2];"
                :: "r"(db), "l"(gb), "r"(mb) : "memory");
        }
    }

    float* rn_out = out + (size_t)Q;
    float* cp_out = out + (size_t)4 * Q;
    float* cf_out = out + (size_t)7 * Q;
    float* bc_out = out + (size_t)8 * Q;

    if (full) {
        // ---- fire-and-forget cooperative gather via cp.async ----
        uint32_t sw_base = (uint32_t)__cvta_generic_to_shared(s_face + wrp * 96);
        int c    = lane & 3;
        int pgrp = lane >> 2;
        #pragma unroll
        for (int r = 0; r < 4; r++) {
            int p_local = 8*r + pgrp;
            int fp = closest_faces[wb + p_local];     // L1-hot broadcast line
            if (c < 3) {
                cp_async16(sw_base + (uint32_t)(p_local * 48 + c * 16),
                           &g_face_pack[4*(size_t)fp + c]);
            }
        }
        asm volatile("cp.async.commit_group;" ::: "memory");

        int f = closest_faces[q];

        // stream data: scalar LDG only for full warps in the (single) partial CTA
        float p0, p1, p2, c0, c1, c2;
        if (!cta_full) {
            c0 = closest_bcs[3*q + 0];
            c1 = closest_bcs[3*q + 1];
            c2 = closest_bcs[3*q + 2];
            p0 = points[3*q + 0];
            p1 = points[3*q + 1];
            p2 = points[3*q + 2];
        }

        asm volatile("cp.async.wait_group 0;" ::: "memory");
        __syncwarp();

        const float4* sw = s_face + wrp * 96;
        float4 v0 = sw[lane*3 + 0];
        float4 v1 = sw[lane*3 + 1];
        float4 v2 = sw[lane*3 + 2];

        if (cta_full) {
            // wait for the TMA bulk loads, then read smem (conflict-free)
            uint32_t done;
            asm volatile(
                "{\n\t.reg .pred p;\n\t"
                "mbarrier.try_wait.parity.acquire.cta.shared::cta.b64 p, [%1], 0;\n\t"
                "selp.b32 %0, 1, 0, p;\n\t}"
                : "=r"(done) : "r"(mb) : "memory");
            if (!done) {
                asm volatile(
                    "{\n\t.reg .pred P1;\n\t"
                    "WL_%=:\n\t"
                    "mbarrier.try_wait.parity.acquire.cta.shared::cta.b64 P1, [%0], 0, 0x989680;\n\t"
                    "@P1 bra.uni WD_%=;\n\t"
                    "bra.uni WL_%=;\n\t"
                    "WD_%=:\n\t}"
                    :: "r"(mb) : "memory");
            }
            const float* sp = (const float*)s_pts4;
            const float* sb = (const float*)s_bcs4;
            p0 = sp[3*tid + 0];
            p1 = sp[3*tid + 1];
            p2 = sp[3*tid + 2];
            c0 = sb[3*tid + 0];
            c1 = sb[3*tid + 1];
            c2 = sb[3*tid + 2];
        }

        float b0 = fminf(fmaxf(c0, 0.0f), 1.0f);
        float b1 = fminf(fmaxf(c1, 0.0f), 1.0f);
        float b2 = fminf(fmaxf(c2, 0.0f), 1.0f);

        // v0=(t00,t01,t02,t10) v1=(t11,t12,t20,t21) v2=(t22,n0,n1,n2)
        float cpx = fmaf(v0.x, b0, fmaf(v0.w, b1, v1.z * b2));
        float cpy = fmaf(v0.y, b0, fmaf(v1.x, b1, v1.w * b2));
        float cpz = fmaf(v0.z, b0, fmaf(v1.y, b1, v2.x * b2));

        float r0 = cpx - p0;
        float r1 = cpy - p1;
        float r2 = cpz - p2;

        float sq   = fmaf(r0, r0, fmaf(r1, r1, r2 * r2));
        float dist = sqrtf(sq);
        float inv  = (dist == 0.0f) ? 1.0f : (1.0f / dist);

        float rn0 = r0 * inv, rn1 = r1 * inv, rn2 = r2 * inv;

        float dot  = fmaf(r0, v2.y, fmaf(r1, v2.z, r2 * v2.w));
        float sign = (dot > 0.0f) ? -1.0f : 1.0f;

        out[q]    = sign * dist;
        cf_out[q] = (float)f;
        rn_out[3*q+0] = rn0; rn_out[3*q+1] = rn1; rn_out[3*q+2] = rn2;
        cp_out[3*q+0] = cpx; cp_out[3*q+1] = cpy; cp_out[3*q+2] = cpz;
        bc_out[3*q+0] = b0;  bc_out[3*q+1] = b1;  bc_out[3*q+2] = b2;
    } else if (q < Q) {
        // scalar fallback (partial warp; Q % 32 == 0 makes this cold)
        int f = closest_faces[q];
        float b0 = fminf(fmaxf(closest_bcs[3*q+0], 0.0f), 1.0f);
        float b1 = fminf(fmaxf(closest_bcs[3*q+1], 0.0f), 1.0f);
        float b2 = fminf(fmaxf(closest_bcs[3*q+2], 0.0f), 1.0f);
        float p0 = points[3*q+0], p1 = points[3*q+1], p2 = points[3*q+2];
        float4 v0 = __ldg(&g_face_pack[4*(size_t)f + 0]);
        float4 v1 = __ldg(&g_face_pack[4*(size_t)f + 1]);
        float4 v2 = __ldg(&g_face_pack[4*(size_t)f + 2]);
        float cpx = fmaf(v0.x, b0, fmaf(v0.w, b1, v1.z * b2));
        float cpy = fmaf(v0.y, b0, fmaf(v1.x, b1, v1.w * b2));
        float cpz = fmaf(v0.z, b0, fmaf(v1.y, b1, v2.x * b2));
        float r0 = cpx - p0, r1 = cpy - p1, r2 = cpz - p2;
        float sq = fmaf(r0, r0, fmaf(r1, r1, r2 * r2));
        float dist = sqrtf(sq);
        float inv = (dist == 0.0f) ? 1.0f : (1.0f / dist);
        float dot = fmaf(r0, v2.y, fmaf(r1, v2.z, r2 * v2.w));
        float sign = (dot > 0.0f) ? -1.0f : 1.0f;
        out[q] = sign * dist;
        cf_out[q] = (float)f;
        rn_out[3*q+0] = r0*inv; rn_out[3*q+1] = r1*inv; rn_out[3*q+2] = r2*inv;
        cp_out[3*q+0] = cpx; cp_out[3*q+1] = cpy; cp_out[3*q+2] = cpz;
        bc_out[3*q+0] = b0;  bc_out[3*q+1] = b1;  bc_out[3*q+2] = b2;
    }
}

extern "C" void kernel_launch(void* const* d_in, const int* in_sizes, int n_in,
                              void* d_out, int out_size) {
    const float* triangles     = (const float*)d_in[0];
    const float* face_normals  = (const float*)d_in[1];
    const float* points        = (const float*)d_in[2];
    const int*   closest_faces = (const int*)d_in[3];
    const float* closest_bcs   = (const float*)d_in[4];
    float* out = (float*)d_out;

    int F = in_sizes[0] / 9;
    int Q = in_sizes[3];

    int Fc = F > FMAX ? FMAX : F;
    repack_kernel<<<(Fc * 3 + 255) / 256, 256>>>(triangles, face_normals, Fc);

    int blocks = (Q + 255) / 256;
    sd_tmald_kernel<<<blocks, 256>>>(points, closest_faces, closest_bcs, out, Q);
}